// round 12
// baseline (speedup 1.0000x reference)
#include <cuda_runtime.h>
#include <cuda_fp16.h>
#include <cstdint>

// Sinkhorn, 32 x 1024 x 1024, tau=1, 10 iterations.
//   E = exp(s); even iter: a_i = 1/sum_j E_ij b_j ; odd iter: b_j = 1/sum_i E_ij a_i
//   out = float(E) * a_i * b_j
// E stored once as fp16 (64 MB). Three launches:
//   k1: streaming exp+pack + rowsum -> a (iter 0); zeroes k2 counters.
//   k2: persistent work-stealing GEMV, iters 1..8. 148 blocks x 1024 thr
//       (1/SM, all co-resident). Each pass = 1024 dynamic tasks (batch x
//       32-row / 32-col group) pulled from a per-pass atomic counter with
//       prefetch; global barrier between passes. Kills the 256/296 = 86.5%
//       static-partition ceiling.
//   k3: column-sliced final — iter 9 (col pass) block-local + output sweep.

#define BATCH 32
#define N 1024
#define TPB 512
#define WPB 16
#define K2B 148
#define K2T 1024

__device__ __half g_E[(size_t)BATCH * N * N];          // 64 MB
__device__ float g_a[BATCH * N];
__device__ float g_b[BATCH * N];
__device__ unsigned g_task[8];                          // per-pass task counters
__device__ unsigned g_gbar;                             // global barrier

__device__ __forceinline__ float2 h2f(uint32_t v) {
    return __half22float2(*reinterpret_cast<__half2*>(&v));
}

// ===========================================================================
// k1: E = exp(s) -> fp16, a_i = 1/rowsum.  grid (128, 32) x 256 thr.
__global__ void k1_exp_rowsum(const float* __restrict__ s) {
    if (blockIdx.x == 0 && blockIdx.y == 0 && threadIdx.x < 9) {
        if (threadIdx.x < 8) g_task[threadIdx.x] = 0u;
        else                 g_gbar = 0u;
    }

    const int w    = threadIdx.x >> 5;
    const int lane = threadIdx.x & 31;
    const int row  = blockIdx.x * 8 + w;
    const int b    = blockIdx.y;
    const size_t base = ((size_t)b * N + row) * N;

    float sum = 0.f;
    #pragma unroll
    for (int k = 0; k < 8; ++k) {
        const int j = (lane + 32 * k) * 4;
        float4 sv = *reinterpret_cast<const float4*>(s + base + j);
        float e0 = __expf(sv.x), e1 = __expf(sv.y);
        float e2 = __expf(sv.z), e3 = __expf(sv.w);
        __half2 p0 = __floats2half2_rn(e0, e1);
        __half2 p1 = __floats2half2_rn(e2, e3);
        uint2 packed;
        packed.x = *reinterpret_cast<uint32_t*>(&p0);
        packed.y = *reinterpret_cast<uint32_t*>(&p1);
        *reinterpret_cast<uint2*>(&g_E[base + j]) = packed;
        sum += (e0 + e1) + (e2 + e3);
    }
    #pragma unroll
    for (int o = 16; o > 0; o >>= 1) sum += __shfl_down_sync(0xFFFFFFFFu, sum, o);
    if (lane == 0) g_a[b * N + row] = 1.0f / sum;
}

// ===========================================================================
// k2: work-stealing GEMV, iterations 1..8. 148 blocks x 1024 threads.
__global__ void __launch_bounds__(K2T, 1) k2_gemv() {
    const int tid  = threadIdx.x;
    const int w    = tid >> 5;
    const int lane = tid & 31;

    __shared__ float shv[N];              // staged a or b (4 KB)
    __shared__ float red[32][36];         // col-task reduce (4.6 KB)
    __shared__ unsigned sh_task[2];

    unsigned gtarget = 0;

    #pragma unroll 1
    for (int p = 0; p < 8; ++p) {
        const bool colp = ((p & 1) == 0);    // p=0 -> iter1 = col pass
        if (tid == 0) sh_task[0] = atomicAdd(&g_task[p], 1u);
        __syncthreads();
        int parity = 0;

        #pragma unroll 1
        while (true) {
            const unsigned t = sh_task[parity];
            if (tid == 0) sh_task[parity ^ 1] = atomicAdd(&g_task[p], 1u);
            if (t >= 1024u) break;
            const int batch = t >> 5;
            const int grp   = t & 31;
            const size_t bN2 = (size_t)batch * N * N;

            // stage the vector this pass consumes (a for col, b for row)
            if (tid < 256) {
                const float4* src = colp
                    ? reinterpret_cast<const float4*>(&g_a[batch * N])
                    : reinterpret_cast<const float4*>(&g_b[batch * N]);
                reinterpret_cast<float4*>(shv)[tid] = __ldcg(&src[tid]);
            }
            __syncthreads();

            if (colp) {
                // task: cols [grp*32, grp*32+32), all 1024 rows.
                // thread: 4 cols (uint2), stripe = tid>>3 (128 stripes x 8 rows)
                const int c0 = grp * 32;
                const int cg = (lane & 7) * 4;
                const int stripe = tid >> 3;
                const size_t cb = bN2 + c0 + cg;
                float a0 = 0.f, a1 = 0.f, a2 = 0.f, a3 = 0.f;
                #pragma unroll
                for (int r8 = 0; r8 < 8; ++r8) {
                    const int r = r8 * 128 + stripe;
                    uint2 u = *reinterpret_cast<const uint2*>(
                        &g_E[cb + (size_t)r * N]);
                    const float av = shv[r];
                    float2 f0 = h2f(u.x), f1 = h2f(u.y);
                    a0 = fmaf(av, f0.x, a0); a1 = fmaf(av, f0.y, a1);
                    a2 = fmaf(av, f1.x, a2); a3 = fmaf(av, f1.y, a3);
                }
                // intra-warp: lanes l, l+8, l+16, l+24 share cols -> fold
                a0 += __shfl_down_sync(0xFFFFFFFFu, a0, 16);
                a1 += __shfl_down_sync(0xFFFFFFFFu, a1, 16);
                a2 += __shfl_down_sync(0xFFFFFFFFu, a2, 16);
                a3 += __shfl_down_sync(0xFFFFFFFFu, a3, 16);
                a0 += __shfl_down_sync(0xFFFFFFFFu, a0, 8);
                a1 += __shfl_down_sync(0xFFFFFFFFu, a1, 8);
                a2 += __shfl_down_sync(0xFFFFFFFFu, a2, 8);
                a3 += __shfl_down_sync(0xFFFFFFFFu, a3, 8);
                if (lane < 8)
                    *reinterpret_cast<float4*>(&red[w][lane * 4]) =
                        make_float4(a0, a1, a2, a3);
                __syncthreads();
                if (tid < 32) {
                    float s = 0.f;
                    #pragma unroll
                    for (int q = 0; q < 32; ++q) s += red[q][tid];
                    g_b[batch * N + c0 + tid] = 1.0f / s;
                }
            } else {
                // task: rows [grp*32, grp*32+32); warp per row.
                const int row = grp * 32 + w;
                const size_t base = bN2 + (size_t)row * N;
                float sum = 0.f;
                #pragma unroll
                for (int k = 0; k < 4; ++k) {
                    const int j = lane * 8 + 256 * k;
                    uint4 u = *reinterpret_cast<const uint4*>(&g_E[base + j]);
                    float4 bv0 = *reinterpret_cast<const float4*>(shv + j);
                    float4 bv1 = *reinterpret_cast<const float4*>(shv + j + 4);
                    float2 f0 = h2f(u.x), f1 = h2f(u.y);
                    float2 f2 = h2f(u.z), f3 = h2f(u.w);
                    sum = fmaf(f0.x, bv0.x, sum); sum = fmaf(f0.y, bv0.y, sum);
                    sum = fmaf(f1.x, bv0.z, sum); sum = fmaf(f1.y, bv0.w, sum);
                    sum = fmaf(f2.x, bv1.x, sum); sum = fmaf(f2.y, bv1.y, sum);
                    sum = fmaf(f3.x, bv1.z, sum); sum = fmaf(f3.y, bv1.w, sum);
                }
                #pragma unroll
                for (int o = 16; o > 0; o >>= 1)
                    sum += __shfl_down_sync(0xFFFFFFFFu, sum, o);
                if (lane == 0) g_a[batch * N + row] = 1.0f / sum;
            }
            parity ^= 1;
            __syncthreads();   // shv/red/sh_task slot safe to reuse
        }

        // global barrier between passes
        gtarget += K2B;
        __threadfence();
        __syncthreads();
        if (tid == 0) {
            atomicAdd(&g_gbar, 1u);
            while (*(volatile unsigned*)&g_gbar < gtarget) { }
            __threadfence();
        }
        __syncthreads();
    }
}

// ===========================================================================
// k3: iter 9 (col pass, block-local) + final output. grid (8, 32) x 512 thr.
__global__ void __launch_bounds__(TPB) k3_final(float* __restrict__ out) {
    __shared__ float sha[N];
    __shared__ float red[WPB][128];
    __shared__ float shb[128];
    const int part = blockIdx.x;
    const int b    = blockIdx.y;
    const int w    = threadIdx.x >> 5;
    const int lane = threadIdx.x & 31;
    const size_t bN2 = (size_t)b * N * N;

    for (int t = threadIdx.x; t < N / 4; t += TPB)
        reinterpret_cast<float4*>(sha)[t] =
            reinterpret_cast<const float4*>(&g_a[b * N])[t];
    __syncthreads();

    // Phase A: iter-9 column sums over this block's 128 cols
    {
        const int col = part * 128 + (lane & 15) * 8;
        const int rofs = w * 2 + (lane >> 4);
        const size_t cb = bN2 + col;
        float acc[8] = {0.f, 0.f, 0.f, 0.f, 0.f, 0.f, 0.f, 0.f};
        #pragma unroll 1
        for (int it4 = 0; it4 < 8; ++it4) {
            uint4 u[4];
            float av[4];
            #pragma unroll
            for (int v = 0; v < 4; ++v) {
                const int r = (it4 * 4 + v) * 32 + rofs;
                u[v]  = *reinterpret_cast<const uint4*>(&g_E[cb + (size_t)r * N]);
                av[v] = sha[r];
            }
            #pragma unroll
            for (int v = 0; v < 4; ++v) {
                float2 f0 = h2f(u[v].x), f1 = h2f(u[v].y);
                float2 f2 = h2f(u[v].z), f3 = h2f(u[v].w);
                acc[0] = fmaf(av[v], f0.x, acc[0]);
                acc[1] = fmaf(av[v], f0.y, acc[1]);
                acc[2] = fmaf(av[v], f1.x, acc[2]);
                acc[3] = fmaf(av[v], f1.y, acc[3]);
                acc[4] = fmaf(av[v], f2.x, acc[4]);
                acc[5] = fmaf(av[v], f2.y, acc[5]);
                acc[6] = fmaf(av[v], f3.x, acc[6]);
                acc[7] = fmaf(av[v], f3.y, acc[7]);
            }
        }
        #pragma unroll
        for (int k = 0; k < 8; ++k)
            acc[k] += __shfl_xor_sync(0xFFFFFFFFu, acc[k], 16);
        if (lane < 16) {
            #pragma unroll
            for (int k = 0; k < 8; ++k) red[w][(lane & 15) * 8 + k] = acc[k];
        }
        __syncthreads();
        if (threadIdx.x < 128) {
            float ssum = 0.f;
            #pragma unroll
            for (int ww = 0; ww < WPB; ++ww) ssum += red[ww][threadIdx.x];
            shb[threadIdx.x] = 1.0f / ssum;
        }
        __syncthreads();
    }

    // Phase B: out = E * a * b (slab L2-hot)
    {
        const int c4 = lane * 4;
        const float4 bv = *reinterpret_cast<const float4*>(&shb[c4]);
        const size_t cbase = bN2 + part * 128 + c4;
        #pragma unroll 1
        for (int t = 0; t < 16; ++t) {
            const int r0 = w * 64 + t * 4;
            uint2  e[4];
            float  av[4];
            #pragma unroll
            for (int v = 0; v < 4; ++v) {
                e[v]  = *reinterpret_cast<const uint2*>(&g_E[cbase + (size_t)(r0 + v) * N]);
                av[v] = sha[r0 + v];
            }
            #pragma unroll
            for (int v = 0; v < 4; ++v) {
                float2 f0 = h2f(e[v].x), f1 = h2f(e[v].y);
                float4 o;
                o.x = f0.x * (av[v] * bv.x);
                o.y = f0.y * (av[v] * bv.y);
                o.z = f1.x * (av[v] * bv.z);
                o.w = f1.y * (av[v] * bv.w);
                *reinterpret_cast<float4*>(out + cbase + (size_t)(r0 + v) * N) = o;
            }
        }
    }
}

// ---------------------------------------------------------------------------
extern "C" void kernel_launch(void* const* d_in, const int* in_sizes, int n_in,
                              void* d_out, int out_size) {
    const float* s = (const float*)d_in[0];
    float* out = (float*)d_out;

    k1_exp_rowsum<<<dim3(128, BATCH), 256>>>(s);
    k2_gemv<<<K2B, K2T>>>();
    k3_final<<<dim3(8, BATCH), TPB>>>(out);
}

// round 13
// speedup vs baseline: 1.1536x; 1.1536x over previous
#include <cuda_runtime.h>
#include <cuda_fp16.h>
#include <cstdint>

// Sinkhorn, 32 x 1024 x 1024, tau=1, 10 iterations.
//   E = exp(s); even iter: a_i = 1/sum_j E_ij b_j ; odd iter: b_j = 1/sum_i E_ij a_i
//   out = float(E) * a_i * b_j
// E stored once as fp16 (64 MB). Three launches:
//   k1: streaming exp+pack + rowsum -> a (iter 0); zeroes k2 barrier.
//   k2: persistent GEMV iters 1..8 on EXACTLY 296 blocks (148 SMs x occ 2 ->
//       100% slot fill; kills the old 256/296 = 86.5% ceiling). Blocks own
//       contiguous GLOBAL row ranges (row passes) / 16-col units (col passes),
//       crossing batch boundaries; global atomic barrier between passes.
//   k3: column-sliced final — iter 9 (col pass) block-local + output sweep.

#define BATCH 32
#define N 1024
#define TPB 512
#define WPB 16
#define K2B 296
#define TOTROWS (BATCH * N)            // 32768 global rows
#define TOTUNITS (BATCH * N / 16)      // 2048 16-col units

__device__ __half g_E[(size_t)BATCH * N * N];          // 64 MB
__device__ float g_a[BATCH * N];
__device__ float g_b[BATCH * N];
__device__ unsigned g_gbar;

__device__ __forceinline__ float2 h2f(uint32_t v) {
    return __half22float2(*reinterpret_cast<__half2*>(&v));
}

// ===========================================================================
// k1: E = exp(s) -> fp16, a_i = 1/rowsum.  grid (128, 32) x 256 thr.
__global__ void k1_exp_rowsum(const float* __restrict__ s) {
    if (blockIdx.x == 0 && blockIdx.y == 0 && threadIdx.x == 0) g_gbar = 0u;

    const int w    = threadIdx.x >> 5;
    const int lane = threadIdx.x & 31;
    const int row  = blockIdx.x * 8 + w;
    const int b    = blockIdx.y;
    const size_t base = ((size_t)b * N + row) * N;

    float sum = 0.f;
    #pragma unroll
    for (int k = 0; k < 8; ++k) {
        const int j = (lane + 32 * k) * 4;
        float4 sv = *reinterpret_cast<const float4*>(s + base + j);
        float e0 = __expf(sv.x), e1 = __expf(sv.y);
        float e2 = __expf(sv.z), e3 = __expf(sv.w);
        __half2 p0 = __floats2half2_rn(e0, e1);
        __half2 p1 = __floats2half2_rn(e2, e3);
        uint2 packed;
        packed.x = *reinterpret_cast<uint32_t*>(&p0);
        packed.y = *reinterpret_cast<uint32_t*>(&p1);
        *reinterpret_cast<uint2*>(&g_E[base + j]) = packed;
        sum += (e0 + e1) + (e2 + e3);
    }
    #pragma unroll
    for (int o = 16; o > 0; o >>= 1) sum += __shfl_down_sync(0xFFFFFFFFu, sum, o);
    if (lane == 0) g_a[b * N + row] = 1.0f / sum;
}

// ===========================================================================
// k2: GEMV iterations 1..8, 296 blocks x 512 threads, occ 2 (all resident).
__global__ void __launch_bounds__(TPB, 2) k2_gemv() {
    const int bid  = blockIdx.x;          // 0..295
    const int tid  = threadIdx.x;
    const int w    = tid >> 5;
    const int lane = tid & 31;

    __shared__ float shv[2 * N];          // up to 2 batches' vector (8 KB)
    __shared__ float red[16][16];         // per-unit col reduce

    unsigned gtarget = 0;
    auto global_barrier = [&]() {
        gtarget += K2B;
        __threadfence();
        __syncthreads();
        if (tid == 0) {
            atomicAdd(&g_gbar, 1u);
            while (*(volatile unsigned*)&g_gbar < gtarget) { }
            __threadfence();
        }
        __syncthreads();
    };

    #pragma unroll 1
    for (int p = 0; p < 8; ++p) {
        if ((p & 1) == 0) {
            // ---- column pass (iters 1,3,5,7): b_j = 1/sum_i a_i E_ij ----
            const int u_lo = (bid * TOTUNITS) / K2B;
            const int u_hi = ((bid + 1) * TOTUNITS) / K2B;
            const int b_lo = (u_lo * 16) >> 10;
            const int b_hi = (u_hi * 16 - 1) >> 10;

            if (tid < 256)
                reinterpret_cast<float4*>(shv)[tid] =
                    __ldcg(&reinterpret_cast<const float4*>(&g_a[b_lo * N])[tid]);
            else if (b_hi != b_lo)
                reinterpret_cast<float4*>(shv)[tid] =
                    __ldcg(&reinterpret_cast<const float4*>(&g_a[b_hi * N])[tid - 256]);
            __syncthreads();

            const int cq     = tid & 3;         // col quad within unit
            const int stripe = tid >> 2;        // 0..127, rows stripe*8..+7
            #pragma unroll 1
            for (int u = u_lo; u < u_hi; ++u) {
                const int G0    = u * 16;
                const int batch = G0 >> 10;
                const int j0    = G0 & (N - 1);
                const int aoff  = (batch - b_lo) << 10;
                const size_t eb = (size_t)batch * N * N + j0 + cq * 4;

                float a0 = 0.f, a1 = 0.f, a2 = 0.f, a3 = 0.f;
                uint2 e[8];
                #pragma unroll
                for (int rr = 0; rr < 8; ++rr)
                    e[rr] = *reinterpret_cast<const uint2*>(
                        &g_E[eb + (size_t)(stripe * 8 + rr) * N]);
                #pragma unroll
                for (int rr = 0; rr < 8; ++rr) {
                    const float av = shv[aoff + stripe * 8 + rr];
                    float2 f0 = h2f(e[rr].x), f1 = h2f(e[rr].y);
                    a0 = fmaf(av, f0.x, a0); a1 = fmaf(av, f0.y, a1);
                    a2 = fmaf(av, f1.x, a2); a3 = fmaf(av, f1.y, a3);
                }
                // fold lanes 4 apart (same cq, different stripes)
                #pragma unroll
                for (int o = 16; o >= 4; o >>= 1) {
                    a0 += __shfl_down_sync(0xFFFFFFFFu, a0, o);
                    a1 += __shfl_down_sync(0xFFFFFFFFu, a1, o);
                    a2 += __shfl_down_sync(0xFFFFFFFFu, a2, o);
                    a3 += __shfl_down_sync(0xFFFFFFFFu, a3, o);
                }
                if (lane < 4)
                    *reinterpret_cast<float4*>(&red[w][lane * 4]) =
                        make_float4(a0, a1, a2, a3);
                __syncthreads();
                if (tid < 16) {
                    float s = 0.f;
                    #pragma unroll
                    for (int q = 0; q < 16; ++q) s += red[q][tid];
                    g_b[G0 + tid] = 1.0f / s;
                }
                __syncthreads();
            }
        } else {
            // ---- row pass (iters 2,4,6,8): a_i = 1/sum_j E_ij b_j ----
            const int r_lo = (bid * TOTROWS) / K2B;
            const int r_hi = ((bid + 1) * TOTROWS) / K2B;
            const int b_lo = r_lo >> 10;
            const int b_hi = (r_hi - 1) >> 10;

            if (tid < 256)
                reinterpret_cast<float4*>(shv)[tid] =
                    __ldcg(&reinterpret_cast<const float4*>(&g_b[b_lo * N])[tid]);
            else if (b_hi != b_lo)
                reinterpret_cast<float4*>(shv)[tid] =
                    __ldcg(&reinterpret_cast<const float4*>(&g_b[b_hi * N])[tid - 256]);
            __syncthreads();

            #pragma unroll 1
            for (int r = r_lo + w; r < r_hi; r += WPB) {
                const int off = ((r >> 10) - b_lo) << 10;
                const size_t base = (size_t)r * N;     // global row-major
                float sum = 0.f;
                #pragma unroll
                for (int k = 0; k < 4; ++k) {
                    const int j = lane * 8 + 256 * k;
                    uint4 u = *reinterpret_cast<const uint4*>(&g_E[base + j]);
                    float4 bv0 = *reinterpret_cast<const float4*>(shv + off + j);
                    float4 bv1 = *reinterpret_cast<const float4*>(shv + off + j + 4);
                    float2 f0 = h2f(u.x), f1 = h2f(u.y);
                    float2 f2 = h2f(u.z), f3 = h2f(u.w);
                    sum = fmaf(f0.x, bv0.x, sum); sum = fmaf(f0.y, bv0.y, sum);
                    sum = fmaf(f1.x, bv0.z, sum); sum = fmaf(f1.y, bv0.w, sum);
                    sum = fmaf(f2.x, bv1.x, sum); sum = fmaf(f2.y, bv1.y, sum);
                    sum = fmaf(f3.x, bv1.z, sum); sum = fmaf(f3.y, bv1.w, sum);
                }
                #pragma unroll
                for (int o = 16; o > 0; o >>= 1)
                    sum += __shfl_down_sync(0xFFFFFFFFu, sum, o);
                if (lane == 0) g_a[r] = 1.0f / sum;
            }
        }
        if (p < 7) global_barrier();
    }
}

// ===========================================================================
// k3: iter 9 (col pass, block-local) + final output. grid (8, 32) x 512 thr.
__global__ void __launch_bounds__(TPB) k3_final(float* __restrict__ out) {
    __shared__ float sha[N];
    __shared__ float red[WPB][128];
    __shared__ float shb[128];
    const int part = blockIdx.x;
    const int b    = blockIdx.y;
    const int w    = threadIdx.x >> 5;
    const int lane = threadIdx.x & 31;
    const size_t bN2 = (size_t)b * N * N;

    for (int t = threadIdx.x; t < N / 4; t += TPB)
        reinterpret_cast<float4*>(sha)[t] =
            reinterpret_cast<const float4*>(&g_a[b * N])[t];
    __syncthreads();

    // Phase A: iter-9 column sums over this block's 128 cols
    {
        const int col = part * 128 + (lane & 15) * 8;
        const int rofs = w * 2 + (lane >> 4);
        const size_t cb = bN2 + col;
        float acc[8] = {0.f, 0.f, 0.f, 0.f, 0.f, 0.f, 0.f, 0.f};
        #pragma unroll 1
        for (int it4 = 0; it4 < 8; ++it4) {
            uint4 u[4];
            float av[4];
            #pragma unroll
            for (int v = 0; v < 4; ++v) {
                const int r = (it4 * 4 + v) * 32 + rofs;
                u[v]  = *reinterpret_cast<const uint4*>(&g_E[cb + (size_t)r * N]);
                av[v] = sha[r];
            }
            #pragma unroll
            for (int v = 0; v < 4; ++v) {
                float2 f0 = h2f(u[v].x), f1 = h2f(u[v].y);
                float2 f2 = h2f(u[v].z), f3 = h2f(u[v].w);
                acc[0] = fmaf(av[v], f0.x, acc[0]);
                acc[1] = fmaf(av[v], f0.y, acc[1]);
                acc[2] = fmaf(av[v], f1.x, acc[2]);
                acc[3] = fmaf(av[v], f1.y, acc[3]);
                acc[4] = fmaf(av[v], f2.x, acc[4]);
                acc[5] = fmaf(av[v], f2.y, acc[5]);
                acc[6] = fmaf(av[v], f3.x, acc[6]);
                acc[7] = fmaf(av[v], f3.y, acc[7]);
            }
        }
        #pragma unroll
        for (int k = 0; k < 8; ++k)
            acc[k] += __shfl_xor_sync(0xFFFFFFFFu, acc[k], 16);
        if (lane < 16) {
            #pragma unroll
            for (int k = 0; k < 8; ++k) red[w][(lane & 15) * 8 + k] = acc[k];
        }
        __syncthreads();
        if (threadIdx.x < 128) {
            float ssum = 0.f;
            #pragma unroll
            for (int ww = 0; ww < WPB; ++ww) ssum += red[ww][threadIdx.x];
            shb[threadIdx.x] = 1.0f / ssum;
        }
        __syncthreads();
    }

    // Phase B: out = E * a * b (slab L2-hot)
    {
        const int c4 = lane * 4;
        const float4 bv = *reinterpret_cast<const float4*>(&shb[c4]);
        const size_t cbase = bN2 + part * 128 + c4;
        #pragma unroll 1
        for (int t = 0; t < 16; ++t) {
            const int r0 = w * 64 + t * 4;
            uint2  e[4];
            float  av[4];
            #pragma unroll
            for (int v = 0; v < 4; ++v) {
                e[v]  = *reinterpret_cast<const uint2*>(&g_E[cbase + (size_t)(r0 + v) * N]);
                av[v] = sha[r0 + v];
            }
            #pragma unroll
            for (int v = 0; v < 4; ++v) {
                float2 f0 = h2f(e[v].x), f1 = h2f(e[v].y);
                float4 o;
                o.x = f0.x * (av[v] * bv.x);
                o.y = f0.y * (av[v] * bv.y);
                o.z = f1.x * (av[v] * bv.z);
                o.w = f1.y * (av[v] * bv.w);
                *reinterpret_cast<float4*>(out + cbase + (size_t)(r0 + v) * N) = o;
            }
        }
    }
}

// ---------------------------------------------------------------------------
extern "C" void kernel_launch(void* const* d_in, const int* in_sizes, int n_in,
                              void* d_out, int out_size) {
    const float* s = (const float*)d_in[0];
    float* out = (float*)d_out;

    k1_exp_rowsum<<<dim3(128, BATCH), 256>>>(s);
    k2_gemv<<<K2B, TPB>>>();
    k3_final<<<dim3(8, BATCH), TPB>>>(out);
}

// round 14
// speedup vs baseline: 1.5495x; 1.3433x over previous
#include <cuda_runtime.h>
#include <cuda_fp16.h>
#include <cuda_fp8.h>
#include <cstdint>

// Sinkhorn, 32 x 1024 x 1024, tau=1, 10 iterations.
//   E = exp(s); even iter: a_i = 1/sum_j E_ij b_j ; odd iter: b_j = 1/sum_i E_ij a_i
//   out = float(E16) * a_i * b_j
// Hybrid-precision E: E8 (fp8 e4m3, 32 MB) feeds iters 1..7 (errors there are
// smoothed ~19x by every dot product and again by each later normalization);
// E16 (fp16, 64 MB) feeds iter 8, iter 9 and the output multiply — the only
// places whose error persists. k2 L2 traffic: 576 -> 288 MB.
//   k1: streaming exp + pack E16 & E8 + rowsum -> a (iter 0); zeroes barriers.
//   k2: persistent GEMV iters 1..8 (R11-proven schedule: 8 blocks/batch,
//       per-batch atomic barrier).
//   k3: column-sliced final — iter 9 (col pass, fp16, block-local) + output.

#define BATCH 32
#define N 1024
#define BPB 8                  // k2 blocks per batch; grid = 8 x 32 = 256
#define TPB 512
#define WPB 16

__device__ __half g_E[(size_t)BATCH * N * N];              // 64 MB fp16
__device__ unsigned char g_E8[(size_t)BATCH * N * N];      // 32 MB fp8 e4m3
__device__ float g_a[BATCH * N];
__device__ float g_b[BATCH * N];
__device__ unsigned g_bar[BATCH * 32];

__device__ __forceinline__ float2 h2f(uint32_t v) {
    return __half22float2(*reinterpret_cast<__half2*>(&v));
}
__device__ __forceinline__ float2 f8x2(unsigned short v) {
    __half2_raw hr = __nv_cvt_fp8x2_to_halfraw2(v, __NV_E4M3);
    return __half22float2(*reinterpret_cast<__half2*>(&hr));
}

// ===========================================================================
// k1: E16/E8 = exp(s), a_i = 1/rowsum.  grid (128, 32) x 256 thr.
__global__ void k1_exp_rowsum(const float* __restrict__ s) {
    if (blockIdx.x == 0 && blockIdx.y == 0 && threadIdx.x < BATCH)
        g_bar[threadIdx.x * 32] = 0u;

    const int w    = threadIdx.x >> 5;
    const int lane = threadIdx.x & 31;
    const int row  = blockIdx.x * 8 + w;
    const int b    = blockIdx.y;
    const size_t base = ((size_t)b * N + row) * N;

    float sum = 0.f;
    #pragma unroll
    for (int k = 0; k < 8; ++k) {
        const int j = (lane + 32 * k) * 4;
        float4 sv = *reinterpret_cast<const float4*>(s + base + j);
        float e0 = __expf(sv.x), e1 = __expf(sv.y);
        float e2 = __expf(sv.z), e3 = __expf(sv.w);
        __half2 p0 = __floats2half2_rn(e0, e1);
        __half2 p1 = __floats2half2_rn(e2, e3);
        uint2 packed;
        packed.x = *reinterpret_cast<uint32_t*>(&p0);
        packed.y = *reinterpret_cast<uint32_t*>(&p1);
        *reinterpret_cast<uint2*>(&g_E[base + j]) = packed;
        unsigned short q0 = __nv_cvt_float2_to_fp8x2(make_float2(e0, e1),
                                                     __NV_SATFINITE, __NV_E4M3);
        unsigned short q1 = __nv_cvt_float2_to_fp8x2(make_float2(e2, e3),
                                                     __NV_SATFINITE, __NV_E4M3);
        *reinterpret_cast<uint32_t*>(&g_E8[base + j]) =
            (uint32_t)q0 | ((uint32_t)q1 << 16);
        sum += (e0 + e1) + (e2 + e3);
    }
    #pragma unroll
    for (int o = 16; o > 0; o >>= 1) sum += __shfl_down_sync(0xFFFFFFFFu, sum, o);
    if (lane == 0) g_a[b * N + row] = 1.0f / sum;
}

// ===========================================================================
// k2: persistent GEMV iterations 1..8 (fp8 for 1..7, fp16 for 8).
__global__ void __launch_bounds__(TPB, 2) k2_gemv() {
    const int part = blockIdx.x;          // 0..7
    const int b    = blockIdx.y;          // 0..31
    const int w    = threadIdx.x >> 5;    // 0..15
    const int lane = threadIdx.x & 31;
    const size_t bN2 = (size_t)b * N * N;

    __shared__ float sh[N];               // a or b staging (4 KB)
    __shared__ float red[WPB][128];       // col-pass reduction (8 KB)

    unsigned bar_target = 0;
    unsigned* const barp = &g_bar[b * 32];

    auto batch_barrier = [&]() {
        __threadfence();
        __syncthreads();
        bar_target += BPB;
        if (threadIdx.x == 0) {
            atomicAdd(barp, 1u);
            while (*(volatile unsigned*)barp < bar_target) { }
            __threadfence();
        }
        __syncthreads();
    };

    #pragma unroll 1
    for (int it = 1; it <= 8; ++it) {
        if (it & 1) {
            // ---- column pass (fp8): b_j = 1/sum_i E_ij a_i. 128 cols/block.
            for (int t = threadIdx.x; t < N / 4; t += TPB)
                reinterpret_cast<float4*>(sh)[t] =
                    __ldcg(&reinterpret_cast<const float4*>(&g_a[b * N])[t]);
            __syncthreads();

            const int col = part * 128 + (lane & 15) * 8;
            const int rofs = w * 2 + (lane >> 4);
            const size_t cb = bN2 + col;
            float acc[8] = {0.f, 0.f, 0.f, 0.f, 0.f, 0.f, 0.f, 0.f};
            #pragma unroll 1
            for (int it4 = 0; it4 < 8; ++it4) {
                uint2 u[4];
                float av[4];
                #pragma unroll
                for (int v = 0; v < 4; ++v) {
                    const int r = (it4 * 4 + v) * 32 + rofs;
                    u[v]  = *reinterpret_cast<const uint2*>(&g_E8[cb + (size_t)r * N]);
                    av[v] = sh[r];
                }
                #pragma unroll
                for (int v = 0; v < 4; ++v) {
                    float2 f0 = f8x2((unsigned short)(u[v].x & 0xFFFFu));
                    float2 f1 = f8x2((unsigned short)(u[v].x >> 16));
                    float2 f2 = f8x2((unsigned short)(u[v].y & 0xFFFFu));
                    float2 f3 = f8x2((unsigned short)(u[v].y >> 16));
                    acc[0] = fmaf(av[v], f0.x, acc[0]);
                    acc[1] = fmaf(av[v], f0.y, acc[1]);
                    acc[2] = fmaf(av[v], f1.x, acc[2]);
                    acc[3] = fmaf(av[v], f1.y, acc[3]);
                    acc[4] = fmaf(av[v], f2.x, acc[4]);
                    acc[5] = fmaf(av[v], f2.y, acc[5]);
                    acc[6] = fmaf(av[v], f3.x, acc[6]);
                    acc[7] = fmaf(av[v], f3.y, acc[7]);
                }
            }
            #pragma unroll
            for (int k = 0; k < 8; ++k)
                acc[k] += __shfl_xor_sync(0xFFFFFFFFu, acc[k], 16);
            if (lane < 16) {
                #pragma unroll
                for (int k = 0; k < 8; ++k) red[w][(lane & 15) * 8 + k] = acc[k];
            }
            __syncthreads();
            if (threadIdx.x < 128) {
                float ssum = 0.f;
                #pragma unroll
                for (int ww = 0; ww < WPB; ++ww) ssum += red[ww][threadIdx.x];
                g_b[b * N + part * 128 + threadIdx.x] = 1.0f / ssum;
            }
        } else {
            // ---- row pass: a_i = 1/sum_j E_ij b_j. Warp per row, 8 rows/warp.
            for (int t = threadIdx.x; t < N / 4; t += TPB)
                reinterpret_cast<float4*>(sh)[t] =
                    __ldcg(&reinterpret_cast<const float4*>(&g_b[b * N])[t]);
            __syncthreads();

            if (it < 8) {
                // fp8 rows (iters 2,4,6)
                #pragma unroll 1
                for (int rr = 0; rr < 8; ++rr) {
                    const int row = part * 128 + rr * WPB + w;
                    const size_t base = bN2 + (size_t)row * N;
                    float sum = 0.f;
                    #pragma unroll
                    for (int k = 0; k < 4; ++k) {
                        const int j = lane * 8 + 256 * k;
                        uint2 u = *reinterpret_cast<const uint2*>(&g_E8[base + j]);
                        float4 bv0 = *reinterpret_cast<const float4*>(sh + j);
                        float4 bv1 = *reinterpret_cast<const float4*>(sh + j + 4);
                        float2 f0 = f8x2((unsigned short)(u.x & 0xFFFFu));
                        float2 f1 = f8x2((unsigned short)(u.x >> 16));
                        float2 f2 = f8x2((unsigned short)(u.y & 0xFFFFu));
                        float2 f3 = f8x2((unsigned short)(u.y >> 16));
                        sum = fmaf(f0.x, bv0.x, sum); sum = fmaf(f0.y, bv0.y, sum);
                        sum = fmaf(f1.x, bv0.z, sum); sum = fmaf(f1.y, bv0.w, sum);
                        sum = fmaf(f2.x, bv1.x, sum); sum = fmaf(f2.y, bv1.y, sum);
                        sum = fmaf(f3.x, bv1.z, sum); sum = fmaf(f3.y, bv1.w, sum);
                    }
                    #pragma unroll
                    for (int o = 16; o > 0; o >>= 1)
                        sum += __shfl_down_sync(0xFFFFFFFFu, sum, o);
                    if (lane == 0) g_a[b * N + row] = 1.0f / sum;
                }
            } else {
                // fp16 rows (iter 8 — feeds the output; must be fp16)
                #pragma unroll 1
                for (int rr = 0; rr < 8; ++rr) {
                    const int row = part * 128 + rr * WPB + w;
                    const size_t base = bN2 + (size_t)row * N;
                    float sum = 0.f;
                    #pragma unroll
                    for (int k = 0; k < 4; ++k) {
                        const int j = lane * 8 + 256 * k;
                        uint4 u = *reinterpret_cast<const uint4*>(&g_E[base + j]);
                        float4 bv0 = *reinterpret_cast<const float4*>(sh + j);
                        float4 bv1 = *reinterpret_cast<const float4*>(sh + j + 4);
                        float2 f0 = h2f(u.x), f1 = h2f(u.y);
                        float2 f2 = h2f(u.z), f3 = h2f(u.w);
                        sum = fmaf(f0.x, bv0.x, sum); sum = fmaf(f0.y, bv0.y, sum);
                        sum = fmaf(f1.x, bv0.z, sum); sum = fmaf(f1.y, bv0.w, sum);
                        sum = fmaf(f2.x, bv1.x, sum); sum = fmaf(f2.y, bv1.y, sum);
                        sum = fmaf(f3.x, bv1.z, sum); sum = fmaf(f3.y, bv1.w, sum);
                    }
                    #pragma unroll
                    for (int o = 16; o > 0; o >>= 1)
                        sum += __shfl_down_sync(0xFFFFFFFFu, sum, o);
                    if (lane == 0) g_a[b * N + row] = 1.0f / sum;
                }
            }
        }
        if (it < 8) batch_barrier();
    }
}

// ===========================================================================
// k3: iter 9 (fp16 col pass, block-local) + final output. grid (8,32) x 512.
__global__ void __launch_bounds__(TPB) k3_final(float* __restrict__ out) {
    __shared__ float sha[N];
    __shared__ float red[WPB][128];
    __shared__ float shb[128];
    const int part = blockIdx.x;
    const int b    = blockIdx.y;
    const int w    = threadIdx.x >> 5;
    const int lane = threadIdx.x & 31;
    const size_t bN2 = (size_t)b * N * N;

    for (int t = threadIdx.x; t < N / 4; t += TPB)
        reinterpret_cast<float4*>(sha)[t] =
            reinterpret_cast<const float4*>(&g_a[b * N])[t];
    __syncthreads();

    // Phase A: iter-9 column sums over this block's 128 cols (fp16)
    {
        const int col = part * 128 + (lane & 15) * 8;
        const int rofs = w * 2 + (lane >> 4);
        const size_t cb = bN2 + col;
        float acc[8] = {0.f, 0.f, 0.f, 0.f, 0.f, 0.f, 0.f, 0.f};
        #pragma unroll 1
        for (int it4 = 0; it4 < 8; ++it4) {
            uint4 u[4];
            float av[4];
            #pragma unroll
            for (int v = 0; v < 4; ++v) {
                const int r = (it4 * 4 + v) * 32 + rofs;
                u[v]  = *reinterpret_cast<const uint4*>(&g_E[cb + (size_t)r * N]);
                av[v] = sha[r];
            }
            #pragma unroll
            for (int v = 0; v < 4; ++v) {
                float2 f0 = h2f(u[v].x), f1 = h2f(u[v].y);
                float2 f2 = h2f(u[v].z), f3 = h2f(u[v].w);
                acc[0] = fmaf(av[v], f0.x, acc[0]);
                acc[1] = fmaf(av[v], f0.y, acc[1]);
                acc[2] = fmaf(av[v], f1.x, acc[2]);
                acc[3] = fmaf(av[v], f1.y, acc[3]);
                acc[4] = fmaf(av[v], f2.x, acc[4]);
                acc[5] = fmaf(av[v], f2.y, acc[5]);
                acc[6] = fmaf(av[v], f3.x, acc[6]);
                acc[7] = fmaf(av[v], f3.y, acc[7]);
            }
        }
        #pragma unroll
        for (int k = 0; k < 8; ++k)
            acc[k] += __shfl_xor_sync(0xFFFFFFFFu, acc[k], 16);
        if (lane < 16) {
            #pragma unroll
            for (int k = 0; k < 8; ++k) red[w][(lane & 15) * 8 + k] = acc[k];
        }
        __syncthreads();
        if (threadIdx.x < 128) {
            float ssum = 0.f;
            #pragma unroll
            for (int ww = 0; ww < WPB; ++ww) ssum += red[ww][threadIdx.x];
            shb[threadIdx.x] = 1.0f / ssum;
        }
        __syncthreads();
    }

    // Phase B: out = E16 * a * b (slab L2-hot)
    {
        const int c4 = lane * 4;
        const float4 bv = *reinterpret_cast<const float4*>(&shb[c4]);
        const size_t cbase = bN2 + part * 128 + c4;
        #pragma unroll 1
        for (int t = 0; t < 16; ++t) {
            const int r0 = w * 64 + t * 4;
            uint2  e[4];
            float  av[4];
            #pragma unroll
            for (int v = 0; v < 4; ++v) {
                e[v]  = *reinterpret_cast<const uint2*>(&g_E[cbase + (size_t)(r0 + v) * N]);
                av[v] = sha[r0 + v];
            }
            #pragma unroll
            for (int v = 0; v < 4; ++v) {
                float2 f0 = h2f(e[v].x), f1 = h2f(e[v].y);
                float4 o;
                o.x = f0.x * (av[v] * bv.x);
                o.y = f0.y * (av[v] * bv.y);
                o.z = f1.x * (av[v] * bv.z);
                o.w = f1.y * (av[v] * bv.w);
                *reinterpret_cast<float4*>(out + cbase + (size_t)(r0 + v) * N) = o;
            }
        }
    }
}

// ---------------------------------------------------------------------------
extern "C" void kernel_launch(void* const* d_in, const int* in_sizes, int n_in,
                              void* d_out, int out_size) {
    const float* s = (const float*)d_in[0];
    float* out = (float*)d_out;

    k1_exp_rowsum<<<dim3(128, BATCH), 256>>>(s);
    k2_gemv<<<dim3(BPB, BATCH), TPB>>>();
    k3_final<<<dim3(8, BATCH), TPB>>>(out);
}

// round 17
// speedup vs baseline: 1.7539x; 1.1319x over previous
#include <cuda_runtime.h>
#include <cuda_fp16.h>
#include <cstdint>

// Sinkhorn, 32 x 1024 x 1024, tau=1, 10 iterations.
//   E = exp(s); even iter: a_i = 1/sum_j E_ij b_j ; odd iter: b_j = 1/sum_i E_ij a_i
//   out = float(E) * a_i * b_j
// E stored once as fp16 (64 MB). Three launches:
//   k1: streaming exp+pack + rowsum -> a (iter 0); zeroes k2 barriers.
//   k2: persistent GEMV iters 1..8 (R11 schedule: 8 blocks/batch, per-batch
//       atomic barrier). Iters 1..7 use native half2 HFMA2 math (E never
//       converted; staged vector pre-packed half2; half2 accumulators of
//       <=32 terms, unpacked to fp32 at the reduction) -> ~2.3x fewer inner
//       instructions. Iter 8 (persists into output) stays fp32.
//   k3: column-sliced final — iter 9 (col pass, fp32 math) + output sweep.

#define BATCH 32
#define N 1024
#define BPB 8
#define TPB 512
#define WPB 16

__device__ __half g_E[(size_t)BATCH * N * N];          // 64 MB
__device__ float g_a[BATCH * N];
__device__ float g_b[BATCH * N];
__device__ unsigned g_bar[BATCH * 32];

__device__ __forceinline__ float2 h2f(uint32_t v) {
    return __half22float2(*reinterpret_cast<__half2*>(&v));
}
__device__ __forceinline__ __half2 u2h(uint32_t v) {
    return *reinterpret_cast<__half2*>(&v);
}

// ===========================================================================
// k1: E = exp(s) -> fp16, a_i = 1/rowsum.  grid (128, 32) x 256 thr.
__global__ void k1_exp_rowsum(const float* __restrict__ s) {
    if (blockIdx.x == 0 && blockIdx.y == 0 && threadIdx.x < BATCH)
        g_bar[threadIdx.x * 32] = 0u;

    const int w    = threadIdx.x >> 5;
    const int lane = threadIdx.x & 31;
    const int row  = blockIdx.x * 8 + w;
    const int b    = blockIdx.y;
    const size_t base = ((size_t)b * N + row) * N;

    float sum = 0.f;
    #pragma unroll
    for (int k = 0; k < 8; ++k) {
        const int j = (lane + 32 * k) * 4;
        float4 sv = *reinterpret_cast<const float4*>(s + base + j);
        float e0 = __expf(sv.x), e1 = __expf(sv.y);
        float e2 = __expf(sv.z), e3 = __expf(sv.w);
        __half2 p0 = __floats2half2_rn(e0, e1);
        __half2 p1 = __floats2half2_rn(e2, e3);
        uint2 packed;
        packed.x = *reinterpret_cast<uint32_t*>(&p0);
        packed.y = *reinterpret_cast<uint32_t*>(&p1);
        *reinterpret_cast<uint2*>(&g_E[base + j]) = packed;
        sum += (e0 + e1) + (e2 + e3);
    }
    #pragma unroll
    for (int o = 16; o > 0; o >>= 1) sum += __shfl_down_sync(0xFFFFFFFFu, sum, o);
    if (lane == 0) g_a[b * N + row] = 1.0f / sum;
}

// ===========================================================================
// k2: persistent GEMV iterations 1..8.
__global__ void __launch_bounds__(TPB, 2) k2_gemv() {
    const int part = blockIdx.x;          // 0..7
    const int b    = blockIdx.y;          // 0..31
    const int w    = threadIdx.x >> 5;    // 0..15
    const int lane = threadIdx.x & 31;
    const size_t bN2 = (size_t)b * N * N;

    __shared__ float    sh[N];            // fp32 b staging (iter 8)
    __shared__ uint32_t shh[N];           // half2 staging: dup-a (col) or
                                          // pair-b [j/2] (row), 4 KB
    __shared__ float red[WPB][128];

    unsigned bar_target = 0;
    unsigned* const barp = &g_bar[b * 32];

    auto batch_barrier = [&]() {
        __threadfence();
        __syncthreads();
        bar_target += BPB;
        if (threadIdx.x == 0) {
            atomicAdd(barp, 1u);
            while (*(volatile unsigned*)barp < bar_target) { }
            __threadfence();
        }
        __syncthreads();
    };

    #pragma unroll 1
    for (int it = 1; it <= 8; ++it) {
        if (it & 1) {
            // ---- column pass (half2): b_j = 1/sum_i E_ij a_i. 128 cols/block.
            // stage a duplicated into half2: shh[r] = half2(a_r, a_r)
            for (int t = threadIdx.x; t < N; t += TPB) {
                const float av = __ldcg(&g_a[b * N + t]);
                __half2 hv = __floats2half2_rn(av, av);
                shh[t] = *reinterpret_cast<uint32_t*>(&hv);
            }
            __syncthreads();

            const int col = part * 128 + (lane & 15) * 8;
            const int rofs = w * 2 + (lane >> 4);
            const size_t cb = bN2 + col;
            __half2 hacc0 = __floats2half2_rn(0.f, 0.f);
            __half2 hacc1 = hacc0, hacc2 = hacc0, hacc3 = hacc0;
            #pragma unroll 1
            for (int it4 = 0; it4 < 8; ++it4) {
                uint4 u[4];
                uint32_t av[4];
                #pragma unroll
                for (int v = 0; v < 4; ++v) {
                    const int r = (it4 * 4 + v) * 32 + rofs;
                    u[v]  = *reinterpret_cast<const uint4*>(&g_E[cb + (size_t)r * N]);
                    av[v] = shh[r];
                }
                #pragma unroll
                for (int v = 0; v < 4; ++v) {
                    const __half2 a2 = u2h(av[v]);
                    hacc0 = __hfma2(a2, u2h(u[v].x), hacc0);
                    hacc1 = __hfma2(a2, u2h(u[v].y), hacc1);
                    hacc2 = __hfma2(a2, u2h(u[v].z), hacc2);
                    hacc3 = __hfma2(a2, u2h(u[v].w), hacc3);
                }
            }
            float acc[8];
            {
                float2 f0 = __half22float2(hacc0);
                float2 f1 = __half22float2(hacc1);
                float2 f2 = __half22float2(hacc2);
                float2 f3 = __half22float2(hacc3);
                acc[0] = f0.x; acc[1] = f0.y; acc[2] = f1.x; acc[3] = f1.y;
                acc[4] = f2.x; acc[5] = f2.y; acc[6] = f3.x; acc[7] = f3.y;
            }
            #pragma unroll
            for (int k = 0; k < 8; ++k)
                acc[k] += __shfl_xor_sync(0xFFFFFFFFu, acc[k], 16);
            if (lane < 16) {
                #pragma unroll
                for (int k = 0; k < 8; ++k) red[w][(lane & 15) * 8 + k] = acc[k];
            }
            __syncthreads();
            if (threadIdx.x < 128) {
                float ssum = 0.f;
                #pragma unroll
                for (int ww = 0; ww < WPB; ++ww) ssum += red[ww][threadIdx.x];
                g_b[b * N + part * 128 + threadIdx.x] = 1.0f / ssum;
            }
        } else if (it < 8) {
            // ---- row pass (half2, iters 2/4/6): a_i = 1/sum_j E_ij b_j ----
            // stage b as half2 pairs: shh[j/2] = half2(b_j, b_{j+1})
            for (int t = threadIdx.x; t < N / 2; t += TPB) {
                float2 bv = __ldcg(reinterpret_cast<const float2*>(&g_b[b * N + t * 2]));
                __half2 hv = __floats2half2_rn(bv.x, bv.y);
                shh[t] = *reinterpret_cast<uint32_t*>(&hv);
            }
            __syncthreads();

            #pragma unroll 1
            for (int rr = 0; rr < 8; ++rr) {
                const int row = part * 128 + rr * WPB + w;
                const size_t base = bN2 + (size_t)row * N;
                __half2 hacc0 = __floats2half2_rn(0.f, 0.f);
                __half2 hacc1 = hacc0, hacc2 = hacc0, hacc3 = hacc0;
                #pragma unroll
                for (int k = 0; k < 4; ++k) {
                    const int j = lane * 8 + 256 * k;
                    uint4 u  = *reinterpret_cast<const uint4*>(&g_E[base + j]);
                    uint4 bh = *reinterpret_cast<const uint4*>(&shh[j >> 1]);
                    hacc0 = __hfma2(u2h(u.x), u2h(bh.x), hacc0);
                    hacc1 = __hfma2(u2h(u.y), u2h(bh.y), hacc1);
                    hacc2 = __hfma2(u2h(u.z), u2h(bh.z), hacc2);
                    hacc3 = __hfma2(u2h(u.w), u2h(bh.w), hacc3);
                }
                float2 f0 = __half22float2(hacc0);
                float2 f1 = __half22float2(hacc1);
                float2 f2 = __half22float2(hacc2);
                float2 f3 = __half22float2(hacc3);
                float sum = ((f0.x + f0.y) + (f1.x + f1.y))
                          + ((f2.x + f2.y) + (f3.x + f3.y));
                #pragma unroll
                for (int o = 16; o > 0; o >>= 1)
                    sum += __shfl_down_sync(0xFFFFFFFFu, sum, o);
                if (lane == 0) g_a[b * N + row] = 1.0f / sum;
            }
        } else {
            // ---- row pass (fp32, iter 8 — persists into output) ----
            for (int t = threadIdx.x; t < N / 4; t += TPB)
                reinterpret_cast<float4*>(sh)[t] =
                    __ldcg(&reinterpret_cast<const float4*>(&g_b[b * N])[t]);
            __syncthreads();

            #pragma unroll 1
            for (int rr = 0; rr < 8; ++rr) {
                const int row = part * 128 + rr * WPB + w;
                const size_t base = bN2 + (size_t)row * N;
                float sum = 0.f;
                #pragma unroll
                for (int k = 0; k < 4; ++k) {
                    const int j = lane * 8 + 256 * k;
                    uint4 u = *reinterpret_cast<const uint4*>(&g_E[base + j]);
                    float4 bv0 = *reinterpret_cast<const float4*>(sh + j);
                    float4 bv1 = *reinterpret_cast<const float4*>(sh + j + 4);
                    float2 f0 = h2f(u.x), f1 = h2f(u.y);
                    float2 f2 = h2f(u.z), f3 = h2f(u.w);
                    sum = fmaf(f0.x, bv0.x, sum); sum = fmaf(f0.y, bv0.y, sum);
                    sum = fmaf(f1.x, bv0.z, sum); sum = fmaf(f1.y, bv0.w, sum);
                    sum = fmaf(f2.x, bv1.x, sum); sum = fmaf(f2.y, bv1.y, sum);
                    sum = fmaf(f3.x, bv1.z, sum); sum = fmaf(f3.y, bv1.w, sum);
                }
                #pragma unroll
                for (int o = 16; o > 0; o >>= 1)
                    sum += __shfl_down_sync(0xFFFFFFFFu, sum, o);
                if (lane == 0) g_a[b * N + row] = 1.0f / sum;
            }
        }
        if (it < 8) batch_barrier();
    }
}

// ===========================================================================
// k3: iter 9 (col pass, fp32, block-local) + final output. grid (8,32) x 512.
__global__ void __launch_bounds__(TPB) k3_final(float* __restrict__ out) {
    __shared__ float sha[N];
    __shared__ float red[WPB][128];
    __shared__ float shb[128];
    const int part = blockIdx.x;
    const int b    = blockIdx.y;
    const int w    = threadIdx.x >> 5;
    const int lane = threadIdx.x & 31;
    const size_t bN2 = (size_t)b * N * N;

    for (int t = threadIdx.x; t < N / 4; t += TPB)
        reinterpret_cast<float4*>(sha)[t] =
            reinterpret_cast<const float4*>(&g_a[b * N])[t];
    __syncthreads();

    // Phase A: iter-9 column sums over this block's 128 cols
    {
        const int col = part * 128 + (lane & 15) * 8;
        const int rofs = w * 2 + (lane >> 4);
        const size_t cb = bN2 + col;
        float acc[8] = {0.f, 0.f, 0.f, 0.f, 0.f, 0.f, 0.f, 0.f};
        #pragma unroll 1
        for (int it4 = 0; it4 < 8; ++it4) {
            uint4 u[4];
            float av[4];
            #pragma unroll
            for (int v = 0; v < 4; ++v) {
                const int r = (it4 * 4 + v) * 32 + rofs;
                u[v]  = *reinterpret_cast<const uint4*>(&g_E[cb + (size_t)r * N]);
                av[v] = sha[r];
            }
            #pragma unroll
            for (int v = 0; v < 4; ++v) {
                float2 f0 = h2f(u[v].x), f1 = h2f(u[v].y);
                float2 f2 = h2f(u[v].z), f3 = h2f(u[v].w);
                acc[0] = fmaf(av[v], f0.x, acc[0]);
                acc[1] = fmaf(av[v], f0.y, acc[1]);
                acc[2] = fmaf(av[v], f1.x, acc[2]);
                acc[3] = fmaf(av[v], f1.y, acc[3]);
                acc[4] = fmaf(av[v], f2.x, acc[4]);
                acc[5] = fmaf(av[v], f2.y, acc[5]);
                acc[6] = fmaf(av[v], f3.x, acc[6]);
                acc[7] = fmaf(av[v], f3.y, acc[7]);
            }
        }
        #pragma unroll
        for (int k = 0; k < 8; ++k)
            acc[k] += __shfl_xor_sync(0xFFFFFFFFu, acc[k], 16);
        if (lane < 16) {
            #pragma unroll
            for (int k = 0; k < 8; ++k) red[w][(lane & 15) * 8 + k] = acc[k];
        }
        __syncthreads();
        if (threadIdx.x < 128) {
            float ssum = 0.f;
            #pragma unroll
            for (int ww = 0; ww < WPB; ++ww) ssum += red[ww][threadIdx.x];
            shb[threadIdx.x] = 1.0f / ssum;
        }
        __syncthreads();
    }

    // Phase B: out = E * a * b (slab L2-hot)
    {
        const int c4 = lane * 4;
        const float4 bv = *reinterpret_cast<const float4*>(&shb[c4]);
        const size_t cbase = bN2 + part * 128 + c4;
        #pragma unroll 1
        for (int t = 0; t < 16; ++t) {
            const int r0 = w * 64 + t * 4;
            uint2  e[4];
            float  av[4];
            #pragma unroll
            for (int v = 0; v < 4; ++v) {
                e[v]  = *reinterpret_cast<const uint2*>(&g_E[cbase + (size_t)(r0 + v) * N]);
                av[v] = sha[r0 + v];
            }
            #pragma unroll
            for (int v = 0; v < 4; ++v) {
                float2 f0 = h2f(e[v].x), f1 = h2f(e[v].y);
                float4 o;
                o.x = f0.x * (av[v] * bv.x);
                o.y = f0.y * (av[v] * bv.y);
                o.z = f1.x * (av[v] * bv.z);
                o.w = f1.y * (av[v] * bv.w);
                *reinterpret_cast<float4*>(out + cbase + (size_t)(r0 + v) * N) = o;
            }
        }
    }
}

// ---------------------------------------------------------------------------
extern "C" void kernel_launch(void* const* d_in, const int* in_sizes, int n_in,
                              void* d_out, int out_size) {
    const float* s = (const float*)d_in[0];
    float* out = (float*)d_out;

    k1_exp_rowsum<<<dim3(128, BATCH), 256>>>(s);
    k2_gemv<<<dim3(BPB, BATCH), TPB>>>();
    k3_final<<<dim3(8, BATCH), TPB>>>(out);
}